// round 9
// baseline (speedup 1.0000x reference)
#include <cuda_runtime.h>
#include <math.h>

#define IMG_H   128
#define IMG_W   128
#define NB      4
#define IMG     (IMG_H * IMG_W)          // 16384
#define NPIX    (NB * IMG)               // 65536
#define NINT    1000
#define STRIPS  8
#define SROWS   16                       // output rows per strip
#define GBLK    (NB * STRIPS)            // 32 blocks (4 img x 8 strips)
#define THREADS 512
#define NWARP   (THREADS / 32)           // 16
#define ST      128                      // smem row stride
#define MAXR    24                       // 16 + 4 halo each side
#define FULLM   0xffffffffu

// One publish line per block, on its own 128B line (stride 8 Pubs).
// pub1: {seq, mapped_min, mapped_max, bits(wsum)}   (single 16B sector store)
// pub2: {seq, cnt}                                   (single 8B sector store)
struct alignas(16) Pub { unsigned x, y, z, w; };
__device__ Pub g_pub1[GBLK * 8];
__device__ Pub g_pub2[GBLK * 8];

__device__ __forceinline__ void st_rel_v4(Pub* p, unsigned a, unsigned b,
                                          unsigned c, unsigned d) {
    asm volatile("st.release.gpu.global.v4.b32 [%0], {%1,%2,%3,%4};"
                 :: "l"(p), "r"(a), "r"(b), "r"(c), "r"(d) : "memory");
}
__device__ __forceinline__ uint4 ld_acq_v4(const Pub* p) {
    uint4 v;
    asm volatile("ld.acquire.gpu.global.v4.b32 {%0,%1,%2,%3}, [%4];"
                 : "=r"(v.x), "=r"(v.y), "=r"(v.z), "=r"(v.w)
                 : "l"(p) : "memory");
    return v;
}
__device__ __forceinline__ void st_rel_v2(Pub* p, unsigned a, unsigned b) {
    asm volatile("st.release.gpu.global.v2.b32 [%0], {%1,%2};"
                 :: "l"(p), "r"(a), "r"(b) : "memory");
}
__device__ __forceinline__ uint2 ld_acq_v2(const Pub* p) {
    uint2 v;
    asm volatile("ld.acquire.gpu.global.v2.b32 {%0,%1}, [%2];"
                 : "=r"(v.x), "=r"(v.y) : "l"(p) : "memory");
    return v;
}
__device__ __forceinline__ unsigned ld_rlx(const unsigned* p) {
    unsigned v;
    asm volatile("ld.relaxed.gpu.global.b32 %0, [%1];" : "=r"(v) : "l"(p) : "memory");
    return v;
}

// Order-preserving float <-> uint map (no NaNs here).
__device__ __forceinline__ unsigned fmap(float f) {
    unsigned b = __float_as_uint(f);
    return (b & 0x80000000u) ? ~b : (b | 0x80000000u);
}
__device__ __forceinline__ float funmap(unsigned u) {
    return __uint_as_float((u & 0x80000000u) ? (u ^ 0x80000000u) : ~u);
}

// Horizontal 9-tap box sums for 4 pixels/lane, entirely in registers.
// v = row[4*lane .. 4*lane+3]; out-of-row taps contribute 0 (edge-corrected).
__device__ __forceinline__ float4 hbox_shfl(float4 v, int lane) {
    float4 p, n;
    p.x = __shfl_up_sync(FULLM, v.x, 1);
    p.y = __shfl_up_sync(FULLM, v.y, 1);
    p.z = __shfl_up_sync(FULLM, v.z, 1);
    p.w = __shfl_up_sync(FULLM, v.w, 1);
    n.x = __shfl_down_sync(FULLM, v.x, 1);
    n.y = __shfl_down_sync(FULLM, v.y, 1);
    n.z = __shfl_down_sync(FULLM, v.z, 1);
    n.w = __shfl_down_sync(FULLM, v.w, 1);
    if (lane == 0)  { p.x = p.y = p.z = p.w = 0.0f; }
    if (lane == 31) { n.x = n.y = n.z = n.w = 0.0f; }
    float4 s;
    s.x = ((p.x + p.y) + (p.z + p.w)) + ((v.x + v.y) + (v.z + v.w)) + n.x;
    s.y = s.x - p.x + n.y;
    s.z = s.y - p.y + n.z;
    s.w = s.z - p.z + n.w;
    return s;
}

__device__ __forceinline__ float wmse_px4(float4 pv, float4 tv) {
    float acc = 0.0f;
    float pp[4] = {pv.x, pv.y, pv.z, pv.w};
    float tt[4] = {tv.x, tv.y, tv.z, tv.w};
    #pragma unroll
    for (int k = 0; k < 4; ++k) {
        float t = tt[k];
        float w = 1.0f;
        if (t >= 0.5f)  w = 2.0f;
        if (t >= 2.0f)  w = 5.0f;
        if (t >= 5.0f)  w = 10.0f;
        if (t >= 10.0f) w = 30.0f;
        float d = pp[k] - t;
        acc += w * d * d;
    }
    return acc;
}

__global__ void __launch_bounds__(THREADS, 1)
fused_loss(const float* __restrict__ pred, const float* __restrict__ tgt,
           float* __restrict__ out) {
    __shared__ float imgA[MAXR * ST];
    __shared__ float imgB[MAXR * ST];
    __shared__ float hsA [MAXR * ST];
    __shared__ float hsB [MAXR * ST];
    __shared__ unsigned wmn[NWARP], wmx[NWARP];
    __shared__ float wws[NWARP];
    __shared__ int   wci[NWARP];
    __shared__ float bc_lo, bc_rdx, bc_w;

    const int tid  = threadIdx.x;
    const int lane = tid & 31;
    const int wid  = tid >> 5;
    const int b    = blockIdx.x;
    const int im   = b >> 3;
    const int strip = b & 7;

    // per-launch sequence number (own slot's previous value + 1; replay-safe)
    const unsigned sq = ld_rlx(&g_pub1[b * 8].x) + 1u;

    const int y0 = strip * SROWS;
    const int lo = max(0, y0 - 4);
    const int hi = min(IMG_H, y0 + SROWS + 4);
    const int nrows = hi - lo;

    // ---- fused load + horizontal filter (regs/shuffles) + wmse ----------
    // Warp wid owns window rows wid and wid+16 (second only if in window).
    float wsum = 0.0f;
    {
        const float4* p4 = (const float4*)(pred + (im * IMG + lo * IMG_W));
        const float4* t4 = (const float4*)(tgt  + (im * IMG + lo * IMG_W));
        const int r1 = wid;
        const int r2 = wid + 16;
        const bool ok2 = (r2 < nrows);          // warp-uniform

        float4 pv1 = p4[r1 * 32 + lane];
        float4 tv1 = t4[r1 * 32 + lane];
        float4 pv2, tv2;
        if (ok2) { pv2 = p4[r2 * 32 + lane]; tv2 = t4[r2 * 32 + lane]; }

        {
            float4 sA = hbox_shfl(pv1, lane);
            float4 sB = hbox_shfl(tv1, lane);
            ((float4*)(imgA + r1 * ST))[lane] = pv1;
            ((float4*)(imgB + r1 * ST))[lane] = tv1;
            ((float4*)(hsA  + r1 * ST))[lane] = sA;
            ((float4*)(hsB  + r1 * ST))[lane] = sB;
            const int gy = lo + r1;
            if (gy >= y0 && gy < y0 + SROWS) wsum += wmse_px4(pv1, tv1);
        }
        if (ok2) {
            float4 sA = hbox_shfl(pv2, lane);
            float4 sB = hbox_shfl(tv2, lane);
            ((float4*)(imgA + r2 * ST))[lane] = pv2;
            ((float4*)(imgB + r2 * ST))[lane] = tv2;
            ((float4*)(hsA  + r2 * ST))[lane] = sA;
            ((float4*)(hsB  + r2 * ST))[lane] = sB;
            const int gy = lo + r2;
            if (gy >= y0 && gy < y0 + SROWS) wsum += wmse_px4(pv2, tv2);
        }
    }
    // wmse warp reduction (off critical path)
    #pragma unroll
    for (int o = 16; o > 0; o >>= 1)
        wsum += __shfl_xor_sync(FULLM, wsum, o);
    if (lane == 0) wws[wid] = wsum;
    __syncthreads();

    // ---- vertical sliding sums + distance (regs), both tensors ----------
    const int x   = tid & 127;
    const int seg = tid >> 7;                // 0..3, 4 rows each
    const int yb  = y0 + seg * 4;
    const int cx  = min(x + 4, IMG_W - 1) - max(x - 4, 0) + 1;

    float dA[4], dB[4];
    float mn = INFINITY, mx = -INFINITY;
    {
        float sA = 0.0f, sB = 0.0f;
        const int wlo = max(0, yb - 4), whi = min(IMG_H - 1, yb + 4);
        for (int yy = wlo; yy <= whi; ++yy) {
            sA += hsA[(yy - lo) * ST + x];
            sB += hsB[(yy - lo) * ST + x];
        }
        #pragma unroll
        for (int k = 0; k < 4; ++k) {
            const int y  = yb + k;
            const int cy = min(y + 4, IMG_H - 1) - max(y - 4, 0) + 1;
            const float inv = 1.0f / (float)(cx * cy);
            const float da = imgA[(y - lo) * ST + x] - sA * inv;
            const float db = imgB[(y - lo) * ST + x] - sB * inv;
            dA[k] = da; dB[k] = db;
            mn = fminf(mn, fminf(da, db));
            mx = fmaxf(mx, fmaxf(da, db));
            if (k < 3) {
                if (y + 5 < IMG_H) { sA += hsA[(y + 5 - lo) * ST + x];
                                     sB += hsB[(y + 5 - lo) * ST + x]; }
                if (y - 4 >= 0)    { sA -= hsA[(y - 4 - lo) * ST + x];
                                     sB -= hsB[(y - 4 - lo) * ST + x]; }
            }
        }
    }

    // ---- REDUX min/max on order-mapped uints ------------------------------
    {
        unsigned umn = __reduce_min_sync(FULLM, fmap(mn));
        unsigned umx = __reduce_max_sync(FULLM, fmap(mx));
        if (lane == 0) { wmn[wid] = umn; wmx[wid] = umx; }
    }
    __syncthreads();

    // ---- warp 0: publish {seq,min,max,wsum} in ONE 16B release store ------
    if (wid == 0) {
        unsigned m1 = (lane < NWARP) ? wmn[lane] : 0xFFFFFFFFu;
        unsigned m2 = (lane < NWARP) ? wmx[lane] : 0u;
        float    ws = (lane < NWARP) ? wws[lane] : 0.0f;
        m1 = __reduce_min_sync(FULLM, m1);
        m2 = __reduce_max_sync(FULLM, m2);
        // lanes >= 16 hold 0 -> offsets 8,4,2,1 land total in lane 0
        ws += __shfl_xor_sync(FULLM, ws, 8);
        ws += __shfl_xor_sync(FULLM, ws, 4);
        ws += __shfl_xor_sync(FULLM, ws, 2);
        ws += __shfl_xor_sync(FULLM, ws, 1);
        if (lane == 0)
            st_rel_v4(&g_pub1[b * 8], sq, m1, m2, __float_as_uint(ws));

        // poll: exactly one line per lane (32 blocks)
        uint4 v1;
        do {
            v1 = ld_acq_v4(&g_pub1[lane * 8]);
        } while (!__all_sync(FULLM, v1.x >= sq));

        unsigned mm1 = __reduce_min_sync(FULLM, v1.y);
        unsigned mm2 = __reduce_max_sync(FULLM, v1.z);
        if (lane == 0) {
            const float flo_ = funmap(mm1);
            const float fhi_ = funmap(mm2);
            bc_lo  = flo_;
            bc_rdx = (float)(NINT - 1) / (fhi_ - flo_);
        }
        if (b == 0) {   // fold global wmse now (overlaps others' CRPS work)
            float w = __uint_as_float(v1.w);
            #pragma unroll
            for (int o = 16; o > 0; o >>= 1)
                w += __shfl_xor_sync(FULLM, w, o);
            if (lane == 0) bc_w = w;
        }
    }
    __syncthreads();
    const float flo  = bc_lo;
    const float frdx = bc_rdx;

    // ---- CRPS counts from register-resident dist pairs (exact ints) ------
    // count = #{ j in [0,NINT) : x_j in [min(dA,dB), max(dA,dB)) }
    int cnt = 0;
    #pragma unroll
    for (int k = 0; k < 4; ++k) {
        const float a = fminf(dA[k], dB[k]);
        const float c = fmaxf(dA[k], dB[k]);
        int ja = __float2int_ru((a - flo) * frdx);
        int jb = __float2int_ru((c - flo) * frdx);
        ja = min(max(ja, 0), NINT);
        jb = min(max(jb, 0), NINT);
        cnt += jb - ja;
    }
    cnt = __reduce_add_sync(FULLM, cnt);
    if (lane == 0) wci[wid] = cnt;
    __syncthreads();

    // ---- publish {seq,cnt} (8B); block 0 folds the final ------------------
    if (wid == 0) {
        int c = (lane < NWARP) ? wci[lane] : 0;
        c = __reduce_add_sync(FULLM, c);
        if (lane == 0) st_rel_v2(&g_pub2[b * 8], sq, (unsigned)c);

        if (b == 0) {
            uint2 v1;
            do {
                v1 = ld_acq_v2(&g_pub2[lane * 8]);
            } while (!__all_sync(FULLM, v1.x >= sq));

            int ct = __reduce_add_sync(FULLM, (int)v1.y);
            if (lane == 0) {
                const float fdx_ = 1.0f / frdx;
                const float wmse = bc_w / (float)NPIX;
                const float crps = (float)((double)ct * (double)fdx_ / (double)NPIX);
                out[0] = 1e-4f * wmse + crps;
            }
        }
    }
}

extern "C" void kernel_launch(void* const* d_in, const int* in_sizes, int n_in,
                              void* d_out, int out_size) {
    (void)in_sizes; (void)n_in; (void)out_size;
    const float* pred = (const float*)d_in[0];
    const float* tgt  = (const float*)d_in[1];
    float* out = (float*)d_out;

    fused_loss<<<GBLK, THREADS>>>(pred, tgt, out);
}

// round 10
// speedup vs baseline: 1.4929x; 1.4929x over previous
#include <cuda_runtime.h>
#include <math.h>

#define IMG_H   128
#define IMG_W   128
#define NB      4
#define IMG     (IMG_H * IMG_W)          // 16384
#define NPIX    (NB * IMG)               // 65536
#define NINT    1000
#define STRIPS  16
#define SROWS   8                        // output rows per strip
#define GBLK    (NB * STRIPS)            // 64 blocks (4 img x 16 strips)
#define THREADS 256
#define NWARP   (THREADS / 32)
#define ST      128                      // smem row stride
#define MAXR    16                       // 8 + 4 halo each side
#define FULLM   0xffffffffu

// One publish line per block, on its own 128B line (stride 8 Pubs).
// pub1: {seq, mapped_min, mapped_max, bits(wsum)}  (single 16B sector store)
struct alignas(16) Pub { unsigned x, y, z, w; };
__device__ Pub g_pub1[GBLK * 8];
// Packed final accumulator, ping-pong by seq&1 (finisher zeroes other slot).
// bits [0,40): sum of cnt (max ~2^27); bits [40,64): arrival count.
__device__ unsigned long long g_acc[2];

__device__ __forceinline__ void st_rel_v4(Pub* p, unsigned a, unsigned b,
                                          unsigned c, unsigned d) {
    asm volatile("st.release.gpu.global.v4.b32 [%0], {%1,%2,%3,%4};"
                 :: "l"(p), "r"(a), "r"(b), "r"(c), "r"(d) : "memory");
}
__device__ __forceinline__ uint4 ld_acq_v4(const Pub* p) {
    uint4 v;
    asm volatile("ld.acquire.gpu.global.v4.b32 {%0,%1,%2,%3}, [%4];"
                 : "=r"(v.x), "=r"(v.y), "=r"(v.z), "=r"(v.w)
                 : "l"(p) : "memory");
    return v;
}
__device__ __forceinline__ unsigned ld_rlx(const unsigned* p) {
    unsigned v;
    asm volatile("ld.relaxed.gpu.global.b32 %0, [%1];" : "=r"(v) : "l"(p) : "memory");
    return v;
}

// Order-preserving float <-> uint map (no NaNs here).
__device__ __forceinline__ unsigned fmap(float f) {
    unsigned b = __float_as_uint(f);
    return (b & 0x80000000u) ? ~b : (b | 0x80000000u);
}
__device__ __forceinline__ float funmap(unsigned u) {
    return __uint_as_float((u & 0x80000000u) ? (u ^ 0x80000000u) : ~u);
}

// Horizontal 9-tap box sums for 4 pixels/lane, entirely in registers.
__device__ __forceinline__ float4 hbox_shfl(float4 v, int lane) {
    float4 p, n;
    p.x = __shfl_up_sync(FULLM, v.x, 1);
    p.y = __shfl_up_sync(FULLM, v.y, 1);
    p.z = __shfl_up_sync(FULLM, v.z, 1);
    p.w = __shfl_up_sync(FULLM, v.w, 1);
    n.x = __shfl_down_sync(FULLM, v.x, 1);
    n.y = __shfl_down_sync(FULLM, v.y, 1);
    n.z = __shfl_down_sync(FULLM, v.z, 1);
    n.w = __shfl_down_sync(FULLM, v.w, 1);
    if (lane == 0)  { p.x = p.y = p.z = p.w = 0.0f; }
    if (lane == 31) { n.x = n.y = n.z = n.w = 0.0f; }
    float4 s;
    s.x = ((p.x + p.y) + (p.z + p.w)) + ((v.x + v.y) + (v.z + v.w)) + n.x;
    s.y = s.x - p.x + n.y;
    s.z = s.y - p.y + n.z;
    s.w = s.z - p.z + n.w;
    return s;
}

__device__ __forceinline__ float wmse_px4(float4 pv, float4 tv) {
    float acc = 0.0f;
    float pp[4] = {pv.x, pv.y, pv.z, pv.w};
    float tt[4] = {tv.x, tv.y, tv.z, tv.w};
    #pragma unroll
    for (int k = 0; k < 4; ++k) {
        float t = tt[k];
        float w = 1.0f;
        if (t >= 0.5f)  w = 2.0f;
        if (t >= 2.0f)  w = 5.0f;
        if (t >= 5.0f)  w = 10.0f;
        if (t >= 10.0f) w = 30.0f;
        float d = pp[k] - t;
        acc += w * d * d;
    }
    return acc;
}

__global__ void __launch_bounds__(THREADS, 1)
fused_loss(const float* __restrict__ pred, const float* __restrict__ tgt,
           float* __restrict__ out) {
    __shared__ float imgA[MAXR * ST];
    __shared__ float imgB[MAXR * ST];
    __shared__ float hsA [MAXR * ST];
    __shared__ float hsB [MAXR * ST];
    __shared__ unsigned wmn[NWARP], wmx[NWARP];
    __shared__ float wws[NWARP];
    __shared__ int   wci[NWARP];
    __shared__ float bc_lo, bc_rdx;

    const int tid  = threadIdx.x;
    const int lane = tid & 31;
    const int wid  = tid >> 5;
    const int b    = blockIdx.x;
    const int im   = b >> 4;
    const int strip = b & 15;

    const int y0 = strip * SROWS;
    const int lo = max(0, y0 - 4);
    const int hi = min(IMG_H, y0 + SROWS + 4);
    const int nrows = hi - lo;

    // ---- fused load + horizontal filter (regs/shuffles) + wmse ----------
    float wsum = 0.0f;
    {
        const float4* p4 = (const float4*)(pred + (im * IMG + lo * IMG_W));
        const float4* t4 = (const float4*)(tgt  + (im * IMG + lo * IMG_W));
        const int r1 = wid;
        const int r2 = wid + 8;
        const bool ok2 = (r2 < nrows);          // warp-uniform

        float4 pv1 = p4[r1 * 32 + lane];
        float4 tv1 = t4[r1 * 32 + lane];
        float4 pv2, tv2;
        if (ok2) { pv2 = p4[r2 * 32 + lane]; tv2 = t4[r2 * 32 + lane]; }

        {
            float4 sA = hbox_shfl(pv1, lane);
            float4 sB = hbox_shfl(tv1, lane);
            ((float4*)(imgA + r1 * ST))[lane] = pv1;
            ((float4*)(imgB + r1 * ST))[lane] = tv1;
            ((float4*)(hsA  + r1 * ST))[lane] = sA;
            ((float4*)(hsB  + r1 * ST))[lane] = sB;
            const int gy = lo + r1;
            if (gy >= y0 && gy < y0 + SROWS) wsum += wmse_px4(pv1, tv1);
        }
        if (ok2) {
            float4 sA = hbox_shfl(pv2, lane);
            float4 sB = hbox_shfl(tv2, lane);
            ((float4*)(imgA + r2 * ST))[lane] = pv2;
            ((float4*)(imgB + r2 * ST))[lane] = tv2;
            ((float4*)(hsA  + r2 * ST))[lane] = sA;
            ((float4*)(hsB  + r2 * ST))[lane] = sB;
            const int gy = lo + r2;
            if (gy >= y0 && gy < y0 + SROWS) wsum += wmse_px4(pv2, tv2);
        }
    }
    // per-launch sequence number (own slot's previous value + 1; replay-safe)
    const unsigned sq = ld_rlx(&g_pub1[b * 8].x) + 1u;

    // wmse warp reduction (off critical path)
    #pragma unroll
    for (int o = 16; o > 0; o >>= 1)
        wsum += __shfl_xor_sync(FULLM, wsum, o);
    if (lane == 0) wws[wid] = wsum;
    __syncthreads();

    // ---- vertical sliding sums + distance (regs), both tensors ----------
    const int x   = tid & 127;
    const int seg = tid >> 7;
    const int yb  = y0 + seg * 4;
    const int cx  = min(x + 4, IMG_W - 1) - max(x - 4, 0) + 1;

    float dA[4], dB[4];
    float mn = INFINITY, mx = -INFINITY;
    {
        float sA = 0.0f, sB = 0.0f;
        const int wlo = max(0, yb - 4), whi = min(IMG_H - 1, yb + 4);
        for (int yy = wlo; yy <= whi; ++yy) {
            sA += hsA[(yy - lo) * ST + x];
            sB += hsB[(yy - lo) * ST + x];
        }
        #pragma unroll
        for (int k = 0; k < 4; ++k) {
            const int y  = yb + k;
            const int cy = min(y + 4, IMG_H - 1) - max(y - 4, 0) + 1;
            const float inv = 1.0f / (float)(cx * cy);
            const float da = imgA[(y - lo) * ST + x] - sA * inv;
            const float db = imgB[(y - lo) * ST + x] - sB * inv;
            dA[k] = da; dB[k] = db;
            mn = fminf(mn, fminf(da, db));
            mx = fmaxf(mx, fmaxf(da, db));
            if (k < 3) {
                if (y + 5 < IMG_H) { sA += hsA[(y + 5 - lo) * ST + x];
                                     sB += hsB[(y + 5 - lo) * ST + x]; }
                if (y - 4 >= 0)    { sA -= hsA[(y - 4 - lo) * ST + x];
                                     sB -= hsB[(y - 4 - lo) * ST + x]; }
            }
        }
    }

    // ---- REDUX min/max on order-mapped uints ------------------------------
    {
        unsigned umn = __reduce_min_sync(FULLM, fmap(mn));
        unsigned umx = __reduce_max_sync(FULLM, fmap(mx));
        if (lane == 0) { wmn[wid] = umn; wmx[wid] = umx; }
    }
    __syncthreads();

    // ---- warp 0: publish {seq,min,max,wsum}; poll; fold lo/dx -------------
    float ww1 = 0.0f, ww2 = 0.0f;    // all 64 wsum partials live here (warp 0)
    if (wid == 0) {
        unsigned m1 = (lane < NWARP) ? wmn[lane] : 0xFFFFFFFFu;
        unsigned m2 = (lane < NWARP) ? wmx[lane] : 0u;
        float    ws = (lane < NWARP) ? wws[lane] : 0.0f;
        m1 = __reduce_min_sync(FULLM, m1);
        m2 = __reduce_max_sync(FULLM, m2);
        ws += __shfl_xor_sync(FULLM, ws, 4);
        ws += __shfl_xor_sync(FULLM, ws, 2);
        ws += __shfl_xor_sync(FULLM, ws, 1);
        if (lane == 0)
            st_rel_v4(&g_pub1[b * 8], sq, m1, m2, __float_as_uint(ws));

        uint4 v1, v2;
        do {
            v1 = ld_acq_v4(&g_pub1[lane * 8]);
            v2 = ld_acq_v4(&g_pub1[(lane + 32) * 8]);
        } while (!__all_sync(FULLM, (v1.x >= sq) && (v2.x >= sq)));

        unsigned mm1 = __reduce_min_sync(FULLM, min(v1.y, v2.y));
        unsigned mm2 = __reduce_max_sync(FULLM, max(v1.z, v2.z));
        if (lane == 0) {
            const float flo_ = funmap(mm1);
            const float fhi_ = funmap(mm2);
            bc_lo  = flo_;
            bc_rdx = (float)(NINT - 1) / (fhi_ - flo_);
        }
        ww1 = __uint_as_float(v1.w);
        ww2 = __uint_as_float(v2.w);
    }
    __syncthreads();
    const float flo  = bc_lo;
    const float frdx = bc_rdx;

    // ---- CRPS counts from register-resident dist pairs (exact ints) ------
    int cnt = 0;
    #pragma unroll
    for (int k = 0; k < 4; ++k) {
        const float a = fminf(dA[k], dB[k]);
        const float c = fmaxf(dA[k], dB[k]);
        int ja = __float2int_ru((a - flo) * frdx);
        int jb = __float2int_ru((c - flo) * frdx);
        ja = min(max(ja, 0), NINT);
        jb = min(max(jb, 0), NINT);
        cnt += jb - ja;
    }
    cnt = __reduce_add_sync(FULLM, cnt);
    if (lane == 0) wci[wid] = cnt;
    __syncthreads();

    // ---- packed atomic tail: last-arriving block already has the total ----
    if (wid == 0) {
        bool is_last = false;
        unsigned long long tot = 0;
        if (lane == 0) {
            int c = 0;
            #pragma unroll
            for (int i = 0; i < NWARP; ++i) c += wci[i];
            unsigned long long add = (1ULL << 40) | (unsigned long long)c;
            unsigned long long prev = atomicAdd(&g_acc[sq & 1u], add);
            is_last = ((prev >> 40) == (unsigned long long)(GBLK - 1));
            tot = (prev & ((1ULL << 40) - 1ULL)) + (unsigned long long)c;
        }
        is_last = __shfl_sync(FULLM, is_last, 0);
        if (is_last) {
            // fold global wmse from register-resident partials (warp 0 only)
            float w = ww1 + ww2;
            #pragma unroll
            for (int o = 16; o > 0; o >>= 1)
                w += __shfl_xor_sync(FULLM, w, o);
            if (lane == 0) {
                g_acc[(sq + 1u) & 1u] = 0ULL;   // reset slot for next launch
                const float fdx_ = 1.0f / frdx;
                const float wmse = w / (float)NPIX;
                const float crps =
                    (float)((double)(long long)tot * (double)fdx_ / (double)NPIX);
                out[0] = 1e-4f * wmse + crps;
            }
        }
    }
}

extern "C" void kernel_launch(void* const* d_in, const int* in_sizes, int n_in,
                              void* d_out, int out_size) {
    (void)in_sizes; (void)n_in; (void)out_size;
    const float* pred = (const float*)d_in[0];
    const float* tgt  = (const float*)d_in[1];
    float* out = (float*)d_out;

    fused_loss<<<GBLK, THREADS>>>(pred, tgt, out);
}

// round 11
// speedup vs baseline: 1.5368x; 1.0294x over previous
#include <cuda_runtime.h>
#include <math.h>

#define IMG_H   128
#define IMG_W   128
#define NB      4
#define IMG     (IMG_H * IMG_W)          // 16384
#define NPIX    (NB * IMG)               // 65536
#define NINT    1000
#define STRIPS  16
#define SROWS   8                        // output rows per strip
#define GBLK    (NB * STRIPS)            // 64 blocks (4 img x 16 strips)
#define THREADS 256
#define NWARP   (THREADS / 32)
#define ST      128                      // smem row stride
#define MAXR    16                       // 8 + 4 halo each side
#define FULLM   0xffffffffu

// One publish line per block, on its own 128B line (stride 8 Pubs).
// pub1: {seq, mapped_min, mapped_max, bits(wsum)}  (single 16B sector store)
struct alignas(16) Pub { unsigned x, y, z, w; };
__device__ Pub g_pub1[GBLK * 8];
// Packed final accumulator, ping-pong by seq&1 (finisher zeroes other slot).
// bits [0,40): sum of cnt (max ~2^26); bits [40,64): block arrival count.
__device__ unsigned long long g_acc[2];

__device__ __forceinline__ void st_rel_v4(Pub* p, unsigned a, unsigned b,
                                          unsigned c, unsigned d) {
    asm volatile("st.release.gpu.global.v4.b32 [%0], {%1,%2,%3,%4};"
                 :: "l"(p), "r"(a), "r"(b), "r"(c), "r"(d) : "memory");
}
__device__ __forceinline__ uint4 ld_acq_v4(const Pub* p) {
    uint4 v;
    asm volatile("ld.acquire.gpu.global.v4.b32 {%0,%1,%2,%3}, [%4];"
                 : "=r"(v.x), "=r"(v.y), "=r"(v.z), "=r"(v.w)
                 : "l"(p) : "memory");
    return v;
}
__device__ __forceinline__ unsigned ld_rlx(const unsigned* p) {
    unsigned v;
    asm volatile("ld.relaxed.gpu.global.b32 %0, [%1];" : "=r"(v) : "l"(p) : "memory");
    return v;
}

// Order-preserving float <-> uint map (no NaNs here).
__device__ __forceinline__ unsigned fmap(float f) {
    unsigned b = __float_as_uint(f);
    return (b & 0x80000000u) ? ~b : (b | 0x80000000u);
}
__device__ __forceinline__ float funmap(unsigned u) {
    return __uint_as_float((u & 0x80000000u) ? (u ^ 0x80000000u) : ~u);
}

// Horizontal 9-tap box sums for 4 pixels/lane, entirely in registers.
__device__ __forceinline__ float4 hbox_shfl(float4 v, int lane) {
    float4 p, n;
    p.x = __shfl_up_sync(FULLM, v.x, 1);
    p.y = __shfl_up_sync(FULLM, v.y, 1);
    p.z = __shfl_up_sync(FULLM, v.z, 1);
    p.w = __shfl_up_sync(FULLM, v.w, 1);
    n.x = __shfl_down_sync(FULLM, v.x, 1);
    n.y = __shfl_down_sync(FULLM, v.y, 1);
    n.z = __shfl_down_sync(FULLM, v.z, 1);
    n.w = __shfl_down_sync(FULLM, v.w, 1);
    if (lane == 0)  { p.x = p.y = p.z = p.w = 0.0f; }
    if (lane == 31) { n.x = n.y = n.z = n.w = 0.0f; }
    float4 s;
    s.x = ((p.x + p.y) + (p.z + p.w)) + ((v.x + v.y) + (v.z + v.w)) + n.x;
    s.y = s.x - p.x + n.y;
    s.z = s.y - p.y + n.z;
    s.w = s.z - p.z + n.w;
    return s;
}

__device__ __forceinline__ float wmse_px4(float4 pv, float4 tv) {
    float acc = 0.0f;
    float pp[4] = {pv.x, pv.y, pv.z, pv.w};
    float tt[4] = {tv.x, tv.y, tv.z, tv.w};
    #pragma unroll
    for (int k = 0; k < 4; ++k) {
        float t = tt[k];
        float w = 1.0f;
        if (t >= 0.5f)  w = 2.0f;
        if (t >= 2.0f)  w = 5.0f;
        if (t >= 5.0f)  w = 10.0f;
        if (t >= 10.0f) w = 30.0f;
        float d = pp[k] - t;
        acc += w * d * d;
    }
    return acc;
}

__global__ void __launch_bounds__(THREADS, 1)
fused_loss(const float* __restrict__ pred, const float* __restrict__ tgt,
           float* __restrict__ out) {
    __shared__ float imgA[MAXR * ST];
    __shared__ float imgB[MAXR * ST];
    __shared__ float hsA [MAXR * ST];
    __shared__ float hsB [MAXR * ST];
    __shared__ unsigned wmn[NWARP], wmx[NWARP];
    __shared__ float wws[NWARP];
    __shared__ float s_wpart[32];        // 32 lanes x (2 polled wsum partials)
    __shared__ float bc_lo, bc_rdx;
    __shared__ int   s_pack;             // (arrivals<<24)|cnt  block merge

    const int tid  = threadIdx.x;
    const int lane = tid & 31;
    const int wid  = tid >> 5;
    const int b    = blockIdx.x;
    const int im   = b >> 4;
    const int strip = b & 15;

    // per-launch sequence number (own slot's previous value + 1; replay-safe)
    const unsigned sq = ld_rlx(&g_pub1[b * 8].x) + 1u;
    if (tid == 0) s_pack = 0;

    const int y0 = strip * SROWS;
    const int lo = max(0, y0 - 4);
    const int hi = min(IMG_H, y0 + SROWS + 4);
    const int nrows = hi - lo;

    // ---- fused load + horizontal filter (regs/shuffles) + wmse ----------
    float wsum = 0.0f;
    {
        const float4* p4 = (const float4*)(pred + (im * IMG + lo * IMG_W));
        const float4* t4 = (const float4*)(tgt  + (im * IMG + lo * IMG_W));
        const int r1 = wid;
        const int r2 = wid + 8;
        const bool ok2 = (r2 < nrows);          // warp-uniform

        float4 pv1 = p4[r1 * 32 + lane];
        float4 tv1 = t4[r1 * 32 + lane];
        float4 pv2, tv2;
        if (ok2) { pv2 = p4[r2 * 32 + lane]; tv2 = t4[r2 * 32 + lane]; }

        {
            float4 sA = hbox_shfl(pv1, lane);
            float4 sB = hbox_shfl(tv1, lane);
            ((float4*)(hsA + r1 * ST))[lane] = sA;
            ((float4*)(hsB + r1 * ST))[lane] = sB;
            const int gy = lo + r1;
            if (gy >= y0 && gy < y0 + SROWS) {   // own row: img + wmse
                ((float4*)(imgA + r1 * ST))[lane] = pv1;
                ((float4*)(imgB + r1 * ST))[lane] = tv1;
                wsum += wmse_px4(pv1, tv1);
            }
        }
        if (ok2) {
            float4 sA = hbox_shfl(pv2, lane);
            float4 sB = hbox_shfl(tv2, lane);
            ((float4*)(hsA + r2 * ST))[lane] = sA;
            ((float4*)(hsB + r2 * ST))[lane] = sB;
            const int gy = lo + r2;
            if (gy >= y0 && gy < y0 + SROWS) {
                ((float4*)(imgA + r2 * ST))[lane] = pv2;
                ((float4*)(imgB + r2 * ST))[lane] = tv2;
                wsum += wmse_px4(pv2, tv2);
            }
        }
    }
    // wmse warp reduction (off critical path)
    #pragma unroll
    for (int o = 16; o > 0; o >>= 1)
        wsum += __shfl_xor_sync(FULLM, wsum, o);
    if (lane == 0) wws[wid] = wsum;
    __syncthreads();

    // ---- vertical sliding sums + distance; keep a=min,c=max in regs ------
    const int x   = tid & 127;
    const int seg = tid >> 7;
    const int yb  = y0 + seg * 4;
    const int cx  = min(x + 4, IMG_W - 1) - max(x - 4, 0) + 1;

    float aR[4], cR[4];                  // per-pixel min/max of (distP, distT)
    float mn = INFINITY, mx = -INFINITY;
    {
        float sA = 0.0f, sB = 0.0f;
        const int wlo = max(0, yb - 4), whi = min(IMG_H - 1, yb + 4);
        for (int yy = wlo; yy <= whi; ++yy) {
            sA += hsA[(yy - lo) * ST + x];
            sB += hsB[(yy - lo) * ST + x];
        }
        #pragma unroll
        for (int k = 0; k < 4; ++k) {
            const int y  = yb + k;
            const int cy = min(y + 4, IMG_H - 1) - max(y - 4, 0) + 1;
            const float inv = 1.0f / (float)(cx * cy);
            const float da = imgA[(y - lo) * ST + x] - sA * inv;
            const float db = imgB[(y - lo) * ST + x] - sB * inv;
            aR[k] = fminf(da, db);
            cR[k] = fmaxf(da, db);
            mn = fminf(mn, aR[k]);
            mx = fmaxf(mx, cR[k]);
            if (k < 3) {
                if (y + 5 < IMG_H) { sA += hsA[(y + 5 - lo) * ST + x];
                                     sB += hsB[(y + 5 - lo) * ST + x]; }
                if (y - 4 >= 0)    { sA -= hsA[(y - 4 - lo) * ST + x];
                                     sB -= hsB[(y - 4 - lo) * ST + x]; }
            }
        }
    }

    // ---- REDUX min/max on order-mapped uints ------------------------------
    {
        unsigned umn = __reduce_min_sync(FULLM, fmap(mn));
        unsigned umx = __reduce_max_sync(FULLM, fmap(mx));
        if (lane == 0) { wmn[wid] = umn; wmx[wid] = umx; }
    }
    __syncthreads();

    // ---- warp 0: publish {seq,min,max,wsum}; poll; fold lo/dx -------------
    if (wid == 0) {
        unsigned m1 = (lane < NWARP) ? wmn[lane] : 0xFFFFFFFFu;
        unsigned m2 = (lane < NWARP) ? wmx[lane] : 0u;
        float    ws = (lane < NWARP) ? wws[lane] : 0.0f;
        m1 = __reduce_min_sync(FULLM, m1);
        m2 = __reduce_max_sync(FULLM, m2);
        ws += __shfl_xor_sync(FULLM, ws, 4);
        ws += __shfl_xor_sync(FULLM, ws, 2);
        ws += __shfl_xor_sync(FULLM, ws, 1);
        if (lane == 0)
            st_rel_v4(&g_pub1[b * 8], sq, m1, m2, __float_as_uint(ws));

        uint4 v1, v2;
        do {
            v1 = ld_acq_v4(&g_pub1[lane * 8]);
            v2 = ld_acq_v4(&g_pub1[(lane + 32) * 8]);
        } while (!__all_sync(FULLM, (v1.x >= sq) && (v2.x >= sq)));

        unsigned mm1 = __reduce_min_sync(FULLM, min(v1.y, v2.y));
        unsigned mm2 = __reduce_max_sync(FULLM, max(v1.z, v2.z));
        if (lane == 0) {
            const float flo_ = funmap(mm1);
            const float fhi_ = funmap(mm2);
            bc_lo  = flo_;
            bc_rdx = (float)(NINT - 1) / (fhi_ - flo_);
        }
        // stash global wsum partials unfolded (1 STS; folded only at the end)
        s_wpart[lane] = __uint_as_float(v1.w) + __uint_as_float(v2.w);
    }
    __syncthreads();
    const float flo  = bc_lo;
    const float frdx = bc_rdx;

    // ---- CRPS counts (exact ints); merge via packed smem atomic -----------
    int cnt = 0;
    #pragma unroll
    for (int k = 0; k < 4; ++k) {
        int ja = __float2int_ru((aR[k] - flo) * frdx);
        int jb = __float2int_ru((cR[k] - flo) * frdx);
        ja = min(max(ja, 0), NINT);
        jb = min(max(jb, 0), NINT);
        cnt += jb - ja;
    }
    cnt = __reduce_add_sync(FULLM, cnt);

    // last-arriving WARP (no block barrier) carries the block total forward;
    // last-arriving BLOCK (packed global atomic) folds wmse and writes out.
    bool last_warp = false;
    int  btot = 0;
    if (lane == 0) {
        int prev = atomicAdd(&s_pack, (1 << 24) + cnt);
        last_warp = ((prev >> 24) == (NWARP - 1));
        btot = (prev & 0xFFFFFF) + cnt;
    }
    last_warp = __shfl_sync(FULLM, last_warp, 0);
    if (last_warp) {
        bool last_blk = false;
        unsigned long long tot = 0;
        if (lane == 0) {
            unsigned long long add = (1ULL << 40) | (unsigned long long)btot;
            unsigned long long prev = atomicAdd(&g_acc[sq & 1u], add);
            last_blk = ((prev >> 40) == (unsigned long long)(GBLK - 1));
            tot = (prev & ((1ULL << 40) - 1ULL)) + (unsigned long long)btot;
        }
        last_blk = __shfl_sync(FULLM, last_blk, 0);
        if (last_blk) {
            float w = s_wpart[lane];
            #pragma unroll
            for (int o = 16; o > 0; o >>= 1)
                w += __shfl_xor_sync(FULLM, w, o);
            if (lane == 0) {
                g_acc[(sq + 1u) & 1u] = 0ULL;   // reset slot for next launch
                const float fdx_ = 1.0f / frdx;
                const float wmse = w / (float)NPIX;
                const float crps =
                    (float)((double)(long long)tot * (double)fdx_ / (double)NPIX);
                out[0] = 1e-4f * wmse + crps;
            }
        }
    }
}

extern "C" void kernel_launch(void* const* d_in, const int* in_sizes, int n_in,
                              void* d_out, int out_size) {
    (void)in_sizes; (void)n_in; (void)out_size;
    const float* pred = (const float*)d_in[0];
    const float* tgt  = (const float*)d_in[1];
    float* out = (float*)d_out;

    fused_loss<<<GBLK, THREADS>>>(pred, tgt, out);
}